// round 6
// baseline (speedup 1.0000x reference)
#include <cuda_runtime.h>
#include <cuda_bf16.h>
#include <math_constants.h>
#include <mma.h>

using namespace nvcuda;

#define BB 2
#define NN 2048
#define HH 8
#define DD 64
#define FIN 512
#define HD 512
#define EPS 1e-5f
#define SCALE 0.125f
#define NW (NN / 32)

// Device scratch
__device__ float g_h[BB * NN * HD];
__device__ float g_S[(size_t)BB * HH * NN * NN];       // unnormalized exp values
__device__ float g_O[BB * NN * HD];
__device__ float g_rowsum[BB * HH * NN];
__device__ unsigned g_mask[(size_t)BB * NN * NW];

__device__ __forceinline__ float f2tf32(float x) {
    float r;
    asm("cvt.rna.tf32.f32 %0, %1;" : "=f"(r) : "f"(x));
    return r;
}

__device__ __forceinline__ void mma_tf32(float d[4], unsigned a0, unsigned a1,
                                         unsigned a2, unsigned a3,
                                         unsigned b0, unsigned b1) {
    asm volatile(
        "mma.sync.aligned.m16n8k8.row.col.f32.tf32.tf32.f32 "
        "{%0,%1,%2,%3}, {%4,%5,%6,%7}, {%8,%9}, {%0,%1,%2,%3};"
        : "+f"(d[0]), "+f"(d[1]), "+f"(d[2]), "+f"(d[3])
        : "r"(a0), "r"(a1), "r"(a2), "r"(a3), "r"(b0), "r"(b1));
}

// ---------------------------------------------------------------------------
// K0: pack adj -> bitmask
// ---------------------------------------------------------------------------
__global__ void k_pack(const int* __restrict__ adj) {
    const int row = blockIdx.x;
    const int t = threadIdx.x;
    const int warp = t >> 5, lane = t & 31;
    const int* arow = adj + (size_t)row * NN;
    #pragma unroll
    for (int j = warp; j < NW; j += 8) {
        unsigned bit = (arow[j * 32 + lane] != 0) ? 1u : 0u;
        unsigned word = __ballot_sync(0xffffffffu, bit);
        if (lane == 0) g_mask[(size_t)row * NW + j] = word;
    }
}

// ---------------------------------------------------------------------------
// K1: h = x @ W + b   (tf32 wmma); outputs rounded to tf32
// ---------------------------------------------------------------------------
__global__ void k_proj(const float* __restrict__ x, const float* __restrict__ W,
                       const float* __restrict__ bias) {
    __shared__ float Xs[64][72];
    __shared__ float Ws[64][72];

    const int t = threadIdx.x;
    const int wid = t >> 5;
    const int warp_m = (wid & 1) * 32;
    const int warp_n = (wid >> 1) * 32;
    const int row0 = blockIdx.y * 64;
    const int col0 = blockIdx.x * 64;

    wmma::fragment<wmma::accumulator, 16, 16, 8, float> c[2][2];
    #pragma unroll
    for (int i = 0; i < 2; i++)
        #pragma unroll
        for (int j = 0; j < 2; j++) wmma::fill_fragment(c[i][j], 0.f);

    for (int k0 = 0; k0 < FIN; k0 += 64) {
        #pragma unroll
        for (int i = 0; i < 8; i++) {
            int idx = t + i * 128;
            int r = idx >> 4, c4 = idx & 15;
            float4 v = *(const float4*)&x[(size_t)(row0 + r) * FIN + k0 + c4 * 4];
            v.x = f2tf32(v.x); v.y = f2tf32(v.y); v.z = f2tf32(v.z); v.w = f2tf32(v.w);
            *(float4*)&Xs[r][c4 * 4] = v;
            float4 w = *(const float4*)&W[(size_t)(k0 + r) * HD + col0 + c4 * 4];
            w.x = f2tf32(w.x); w.y = f2tf32(w.y); w.z = f2tf32(w.z); w.w = f2tf32(w.w);
            *(float4*)&Ws[r][c4 * 4] = w;
        }
        __syncthreads();
        #pragma unroll
        for (int kk = 0; kk < 8; kk++) {
            wmma::fragment<wmma::matrix_a, 16, 16, 8, wmma::precision::tf32, wmma::row_major> a[2];
            wmma::fragment<wmma::matrix_b, 16, 16, 8, wmma::precision::tf32, wmma::row_major> bfr[2];
            #pragma unroll
            for (int i = 0; i < 2; i++)
                wmma::load_matrix_sync(a[i], &Xs[warp_m + 16 * i][kk * 8], 72);
            #pragma unroll
            for (int j = 0; j < 2; j++)
                wmma::load_matrix_sync(bfr[j], &Ws[kk * 8][warp_n + 16 * j], 72);
            #pragma unroll
            for (int i = 0; i < 2; i++)
                #pragma unroll
                for (int j = 0; j < 2; j++)
                    wmma::mma_sync(c[i][j], a[i], bfr[j], c[i][j]);
        }
        __syncthreads();
    }

    __shared__ float Stage[64][72];
    #pragma unroll
    for (int i = 0; i < 2; i++)
        #pragma unroll
        for (int j = 0; j < 2; j++)
            wmma::store_matrix_sync(&Stage[warp_m + 16 * i][warp_n + 16 * j], c[i][j], 72,
                                    wmma::mem_row_major);
    __syncthreads();
    #pragma unroll
    for (int i = 0; i < 8; i++) {
        int idx = t + i * 128;
        int r = idx >> 4, c4 = idx & 15;
        float4 v = *(float4*)&Stage[r][c4 * 4];
        float4 bb = *(const float4*)&bias[col0 + c4 * 4];
        v.x = f2tf32(v.x + bb.x); v.y = f2tf32(v.y + bb.y);
        v.z = f2tf32(v.z + bb.z); v.w = f2tf32(v.w + bb.w);
        *(float4*)&g_h[(size_t)(row0 + r) * HD + col0 + c4 * 4] = v;
    }
}

// ---------------------------------------------------------------------------
// K2: register-resident fused attention with fragment-order smem packing
// CTA: 512 threads / 16 warps; 256-row tile; m-loop 64-chunks.
// smem: stg[2][64*68] raw cp.async staging, SK (S-phase pack), VP (V-phase pack)
// ---------------------------------------------------------------------------
#define STGS 68          // staging row stride (floats)
#define SK_Q 10          // SK q-stride (float2)
#define SK_R 42          // SK row-stride (float2)
#define VP_Q 68          // VP q-stride (float2)
#define VP_KC 272        // VP kc-stride (float2)
// float offsets in dynamic smem
#define OFF_STG1 4352
#define OFF_SK   8704
#define OFF_VP   14080
#define SMEM_FLOATS 18432

__global__ __launch_bounds__(512, 1) void k_fused() {
    extern __shared__ float sm[];
    float* stg0 = sm;
    float* stg1 = sm + OFF_STG1;
    float2* SK = (float2*)(sm + OFF_SK);
    float2* VP = (float2*)(sm + OFF_VP);
    float* VPf = (float*)VP;

    const int t = threadIdx.x;
    const int lane = t & 31;
    const int wid = t >> 5;
    const int g = lane >> 2;
    const int q = lane & 3;
    const int row0 = blockIdx.x * 256;
    const int bh = blockIdx.y;
    const int b = bh >> 3, hh = bh & 7;

    const float* Hb = g_h + (size_t)b * NN * HD + hh * DD;
    const int r_lo = row0 + wid * 16 + g;
    const int r_hi = r_lo + 8;

    // pack-role indices
    const int lr = t >> 3;            // 0..63 tile row
    const int ls = t & 7;             // kc segment
    const int kcr = lr >> 3, rem = lr & 7;
    const int rem4 = rem & 3, hi = rem >> 2;

    // prefetch tile 0
    {
        #pragma unroll
        for (int k = 0; k < 2; k++) {
            int c = t + k * 512;
            int r = c >> 4, seg = c & 15;
            unsigned dst = (unsigned)__cvta_generic_to_shared(&stg0[r * STGS + seg * 4]);
            const float* src = &Hb[(size_t)r * HD + seg * 4];
            asm volatile("cp.async.ca.shared.global [%0], [%1], 16;" :: "r"(dst), "l"(src));
        }
        asm volatile("cp.async.commit_group;");
    }

    // Q fragments (g_h pre-rounded to tf32)
    unsigned Qa[8][4];
    #pragma unroll
    for (int kc = 0; kc < 8; kc++) {
        Qa[kc][0] = __float_as_uint(Hb[(size_t)r_lo * HD + 8 * kc + q]);
        Qa[kc][1] = __float_as_uint(Hb[(size_t)r_hi * HD + 8 * kc + q]);
        Qa[kc][2] = __float_as_uint(Hb[(size_t)r_lo * HD + 8 * kc + q + 4]);
        Qa[kc][3] = __float_as_uint(Hb[(size_t)r_hi * HD + 8 * kc + q + 4]);
    }

    float Oa[8][4];
    #pragma unroll
    for (int f = 0; f < 8; f++)
        #pragma unroll
        for (int e = 0; e < 4; e++) Oa[f][e] = 0.f;
    float rs_lo = 0.f, rs_hi = 0.f;

    const unsigned* mrow_lo = &g_mask[((size_t)b * NN + r_lo) * NW];
    const unsigned* mrow_hi = &g_mask[((size_t)b * NN + r_hi) * NW];
    float* Srow_lo = &g_S[((size_t)bh * NN + r_lo) * NN];
    float* Srow_hi = &g_S[((size_t)bh * NN + r_hi) * NN];

    for (int it = 0; it < 32; it++) {
        const int m0 = it * 64;
        asm volatile("cp.async.wait_group 0;");
        __syncthreads();

        // ---- repack: staging -> SK / VP ----
        float* stgc = (it & 1) ? stg1 : stg0;
        float4 va = *(float4*)&stgc[lr * STGS + ls * 8];
        float4 vb = *(float4*)&stgc[lr * STGS + ls * 8 + 4];

        if (it < 31) {
            float* stgn = (it & 1) ? stg0 : stg1;
            #pragma unroll
            for (int k = 0; k < 2; k++) {
                int c = t + k * 512;
                int r = c >> 4, seg = c & 15;
                unsigned dst = (unsigned)__cvta_generic_to_shared(&stgn[r * STGS + seg * 4]);
                const float* src = &Hb[(size_t)(m0 + 64 + r) * HD + seg * 4];
                asm volatile("cp.async.ca.shared.global [%0], [%1], 16;" :: "r"(dst), "l"(src));
            }
            asm volatile("cp.async.commit_group;");
        }

        float v[8] = {va.x, va.y, va.z, va.w, vb.x, vb.y, vb.z, vb.w};
        #pragma unroll
        for (int qq = 0; qq < 4; qq++)
            SK[lr * SK_R + qq * SK_Q + ls] = make_float2(v[qq], v[qq + 4]);
        #pragma unroll
        for (int j = 0; j < 8; j++)
            VPf[2 * (kcr * VP_KC + rem4 * VP_Q + 8 * ls + j) + hi] = v[j];
        __syncthreads();

        // mask words
        const unsigned m00 = __ldg(&mrow_lo[it * 2]);
        const unsigned m01 = __ldg(&mrow_lo[it * 2 + 1]);
        const unsigned m10 = __ldg(&mrow_hi[it * 2]);
        const unsigned m11 = __ldg(&mrow_hi[it * 2 + 1]);

        // ---- S = Q K^T (B fragments: 4x LDS.128 per f) ----
        float Sa[8][4];
        #pragma unroll
        for (int f = 0; f < 8; f++)
            #pragma unroll
            for (int e = 0; e < 4; e++) Sa[f][e] = 0.f;

        #pragma unroll
        for (int f = 0; f < 8; f++) {
            const float2* skp = &SK[(8 * f + g) * SK_R + q * SK_Q];
            float4 p0 = *(const float4*)&skp[0];
            float4 p1 = *(const float4*)&skp[2];
            float4 p2 = *(const float4*)&skp[4];
            float4 p3 = *(const float4*)&skp[6];
            mma_tf32(Sa[f], Qa[0][0], Qa[0][1], Qa[0][2], Qa[0][3],
                     __float_as_uint(p0.x), __float_as_uint(p0.y));
            mma_tf32(Sa[f], Qa[1][0], Qa[1][1], Qa[1][2], Qa[1][3],
                     __float_as_uint(p0.z), __float_as_uint(p0.w));
            mma_tf32(Sa[f], Qa[2][0], Qa[2][1], Qa[2][2], Qa[2][3],
                     __float_as_uint(p1.x), __float_as_uint(p1.y));
            mma_tf32(Sa[f], Qa[3][0], Qa[3][1], Qa[3][2], Qa[3][3],
                     __float_as_uint(p1.z), __float_as_uint(p1.w));
            mma_tf32(Sa[f], Qa[4][0], Qa[4][1], Qa[4][2], Qa[4][3],
                     __float_as_uint(p2.x), __float_as_uint(p2.y));
            mma_tf32(Sa[f], Qa[5][0], Qa[5][1], Qa[5][2], Qa[5][3],
                     __float_as_uint(p2.z), __float_as_uint(p2.w));
            mma_tf32(Sa[f], Qa[6][0], Qa[6][1], Qa[6][2], Qa[6][3],
                     __float_as_uint(p3.x), __float_as_uint(p3.y));
            mma_tf32(Sa[f], Qa[7][0], Qa[7][1], Qa[7][2], Qa[7][3],
                     __float_as_uint(p3.z), __float_as_uint(p3.w));
        }

        // ---- mask + exp + rowsum + stream E ----
        #pragma unroll
        for (int f = 0; f < 8; f++) {
            const unsigned wlo = (f < 4) ? m00 : m01;
            const unsigned whi = (f < 4) ? m10 : m11;
            const int sh = (8 * f + 2 * q) & 31;
            float e0 = ((wlo >> sh) & 1u)       ? f2tf32(__expf(Sa[f][0] * SCALE)) : 0.f;
            float e1 = ((wlo >> (sh + 1)) & 1u) ? f2tf32(__expf(Sa[f][1] * SCALE)) : 0.f;
            float e2 = ((whi >> sh) & 1u)       ? f2tf32(__expf(Sa[f][2] * SCALE)) : 0.f;
            float e3 = ((whi >> (sh + 1)) & 1u) ? f2tf32(__expf(Sa[f][3] * SCALE)) : 0.f;
            rs_lo += e0 + e1;
            rs_hi += e2 + e3;
            Sa[f][0] = e0; Sa[f][1] = e1; Sa[f][2] = e2; Sa[f][3] = e3;
            __stcs((float2*)&Srow_lo[m0 + 8 * f + 2 * q], make_float2(e0, e1));
            __stcs((float2*)&Srow_hi[m0 + 8 * f + 2 * q], make_float2(e2, e3));
        }

        // ---- O += E V (B fragments: LDS.64 from VP) ----
        const int src1 = (lane & ~3) | (q >> 1);
        const int src2 = src1 + 2;
        const bool odd = q & 1;
        #pragma unroll
        for (int kc = 0; kc < 8; kc++) {
            float c0 = Sa[kc][0], c1 = Sa[kc][1], c2 = Sa[kc][2], c3 = Sa[kc][3];
            float v00 = __shfl_sync(0xffffffffu, c0, src1);
            float v01 = __shfl_sync(0xffffffffu, c1, src1);
            float v02 = __shfl_sync(0xffffffffu, c2, src1);
            float v03 = __shfl_sync(0xffffffffu, c3, src1);
            float v10 = __shfl_sync(0xffffffffu, c0, src2);
            float v11 = __shfl_sync(0xffffffffu, c1, src2);
            float v12 = __shfl_sync(0xffffffffu, c2, src2);
            float v13 = __shfl_sync(0xffffffffu, c3, src2);
            unsigned a0 = __float_as_uint(odd ? v01 : v00);
            unsigned a1 = __float_as_uint(odd ? v03 : v02);
            unsigned a2 = __float_as_uint(odd ? v11 : v10);
            unsigned a3 = __float_as_uint(odd ? v13 : v12);
            const float2* vpp = &VP[kc * VP_KC + q * VP_Q + g];
            #pragma unroll
            for (int df = 0; df < 8; df++) {
                float2 bb = vpp[8 * df];
                mma_tf32(Oa[df], a0, a1, a2, a3,
                         __float_as_uint(bb.x), __float_as_uint(bb.y));
            }
        }
    }

    // ---- epilogue ----
    rs_lo += __shfl_xor_sync(0xffffffffu, rs_lo, 1);
    rs_lo += __shfl_xor_sync(0xffffffffu, rs_lo, 2);
    rs_hi += __shfl_xor_sync(0xffffffffu, rs_hi, 1);
    rs_hi += __shfl_xor_sync(0xffffffffu, rs_hi, 2);
    if (q == 0) {
        g_rowsum[(size_t)bh * NN + r_lo] = rs_lo;
        g_rowsum[(size_t)bh * NN + r_hi] = rs_hi;
    }
    const float inv_lo = 1.f / rs_lo;
    const float inv_hi = 1.f / rs_hi;
    float* O_lo = &g_O[((size_t)b * NN + r_lo) * HD + hh * DD];
    float* O_hi = &g_O[((size_t)b * NN + r_hi) * HD + hh * DD];
    #pragma unroll
    for (int df = 0; df < 8; df++) {
        *(float2*)&O_lo[8 * df + 2 * q] = make_float2(Oa[df][0] * inv_lo, Oa[df][1] * inv_lo);
        *(float2*)&O_hi[8 * df + 2 * q] = make_float2(Oa[df][2] * inv_hi, Oa[df][3] * inv_hi);
    }
}

// ---------------------------------------------------------------------------
// K3: mean over heads of p = e / rowsum  -> out_mean
// ---------------------------------------------------------------------------
__global__ void k_mean(float* __restrict__ out_mean) {
    __shared__ float inv[HH];
    const int row = blockIdx.x;
    const int b = row >> 11;
    const int n = row & (NN - 1);
    const int t = threadIdx.x;

    if (t < HH) inv[t] = 0.125f / g_rowsum[(size_t)(b * HH + t) * NN + n];
    __syncthreads();

    float* mrow = out_mean + (size_t)row * NN;
    #pragma unroll
    for (int c4 = t; c4 < NN / 4; c4 += 256) {
        float4 acc = make_float4(0.f, 0.f, 0.f, 0.f);
        #pragma unroll
        for (int h = 0; h < HH; h++) {
            const float4 e4 = __ldcs((const float4*)&g_S[((size_t)(b * HH + h) * NN + n) * NN + c4 * 4]);
            float iv = inv[h];
            acc.x += e4.x * iv; acc.y += e4.y * iv;
            acc.z += e4.z * iv; acc.w += e4.w * iv;
        }
        *(float4*)&mrow[c4 * 4] = acc;
    }
}

// ---------------------------------------------------------------------------
// K5: LayerNorm -> out
// ---------------------------------------------------------------------------
__global__ void k_ln(const float* __restrict__ gamma, const float* __restrict__ beta,
                     float* __restrict__ out) {
    __shared__ float red[128];
    __shared__ float red2[128];

    const int row = blockIdx.x;
    const int t = threadIdx.x;
    const float* v = g_O + (size_t)row * HD;

    float s = 0.f, s2 = 0.f;
    float vals[4];
    #pragma unroll
    for (int i = 0; i < 4; i++) {
        vals[i] = v[t + i * 128];
        s += vals[i];
        s2 += vals[i] * vals[i];
    }
    red[t] = s; red2[t] = s2;
    __syncthreads();
    for (int st = 64; st > 0; st >>= 1) {
        if (t < st) { red[t] += red[t + st]; red2[t] += red2[t + st]; }
        __syncthreads();
    }
    const float mu = red[0] * (1.f / HD);
    const float var = red2[0] * (1.f / HD) - mu * mu;
    const float rstd = rsqrtf(var + EPS);

    float* orow = out + (size_t)row * HD;
    #pragma unroll
    for (int i = 0; i < 4; i++) {
        int c = t + i * 128;
        orow[c] = (vals[i] - mu) * rstd * gamma[c] + beta[c];
    }
}

// ---------------------------------------------------------------------------
extern "C" void kernel_launch(void* const* d_in, const int* in_sizes, int n_in,
                              void* d_out, int out_size) {
    const float* x     = (const float*)d_in[0];
    const int*   adj   = (const int*)d_in[1];
    const float* W_w   = (const float*)d_in[2];
    const float* W_b   = (const float*)d_in[3];
    const float* gamma = (const float*)d_in[4];
    const float* beta  = (const float*)d_in[5];
    float* out = (float*)d_out;
    float* out_mean = out + (size_t)BB * NN * HD;

    const int SMEMB = SMEM_FLOATS * 4;   // 73728 B
    cudaFuncSetAttribute(k_fused, cudaFuncAttributeMaxDynamicSharedMemorySize, SMEMB);

    k_pack<<<BB * NN, 256>>>(adj);
    k_proj<<<dim3(HD / 64, (BB * NN) / 64), 128>>>(x, W_w, W_b);
    k_fused<<<dim3(NN / 256, BB * HH), 512, SMEMB>>>();
    k_mean<<<BB * NN, 256>>>(out_mean);
    k_ln<<<BB * NN, 128>>>(gamma, beta, out);
}

// round 7
// speedup vs baseline: 1.2447x; 1.2447x over previous
#include <cuda_runtime.h>
#include <cuda_bf16.h>
#include <math_constants.h>
#include <mma.h>

using namespace nvcuda;

#define BB 2
#define NN 2048
#define HH 8
#define DD 64
#define FIN 512
#define HD 512
#define EPS 1e-5f
#define SCALE 0.125f
#define NW (NN / 32)

// Device scratch
__device__ float g_h[BB * NN * HD];
__device__ float g_S[(size_t)BB * HH * NN * NN];       // unnormalized exp values
__device__ float g_O[BB * NN * HD];
__device__ float g_rowsum[BB * HH * NN];
__device__ unsigned g_mask[(size_t)BB * NN * NW];

__device__ __forceinline__ float f2tf32(float x) {
    float r;
    asm("cvt.rna.tf32.f32 %0, %1;" : "=f"(r) : "f"(x));
    return r;
}

__device__ __forceinline__ void mma_tf32(float d[4], unsigned a0, unsigned a1,
                                         unsigned a2, unsigned a3,
                                         unsigned b0, unsigned b1) {
    asm volatile(
        "mma.sync.aligned.m16n8k8.row.col.f32.tf32.tf32.f32 "
        "{%0,%1,%2,%3}, {%4,%5,%6,%7}, {%8,%9}, {%0,%1,%2,%3};"
        : "+f"(d[0]), "+f"(d[1]), "+f"(d[2]), "+f"(d[3])
        : "r"(a0), "r"(a1), "r"(a2), "r"(a3), "r"(b0), "r"(b1));
}

// ---------------------------------------------------------------------------
// K0: pack adj -> bitmask
// ---------------------------------------------------------------------------
__global__ void k_pack(const int* __restrict__ adj) {
    const int row = blockIdx.x;
    const int t = threadIdx.x;
    const int warp = t >> 5, lane = t & 31;
    const int* arow = adj + (size_t)row * NN;
    #pragma unroll
    for (int j = warp; j < NW; j += 8) {
        unsigned bit = (arow[j * 32 + lane] != 0) ? 1u : 0u;
        unsigned word = __ballot_sync(0xffffffffu, bit);
        if (lane == 0) g_mask[(size_t)row * NW + j] = word;
    }
}

// ---------------------------------------------------------------------------
// K1: h = x @ W + b   (tf32 wmma); outputs rounded to tf32
// ---------------------------------------------------------------------------
__global__ void k_proj(const float* __restrict__ x, const float* __restrict__ W,
                       const float* __restrict__ bias) {
    __shared__ float Xs[64][72];
    __shared__ float Ws[64][72];

    const int t = threadIdx.x;
    const int wid = t >> 5;
    const int warp_m = (wid & 1) * 32;
    const int warp_n = (wid >> 1) * 32;
    const int row0 = blockIdx.y * 64;
    const int col0 = blockIdx.x * 64;

    wmma::fragment<wmma::accumulator, 16, 16, 8, float> c[2][2];
    #pragma unroll
    for (int i = 0; i < 2; i++)
        #pragma unroll
        for (int j = 0; j < 2; j++) wmma::fill_fragment(c[i][j], 0.f);

    for (int k0 = 0; k0 < FIN; k0 += 64) {
        #pragma unroll
        for (int i = 0; i < 8; i++) {
            int idx = t + i * 128;
            int r = idx >> 4, c4 = idx & 15;
            float4 v = *(const float4*)&x[(size_t)(row0 + r) * FIN + k0 + c4 * 4];
            v.x = f2tf32(v.x); v.y = f2tf32(v.y); v.z = f2tf32(v.z); v.w = f2tf32(v.w);
            *(float4*)&Xs[r][c4 * 4] = v;
            float4 w = *(const float4*)&W[(size_t)(k0 + r) * HD + col0 + c4 * 4];
            w.x = f2tf32(w.x); w.y = f2tf32(w.y); w.z = f2tf32(w.z); w.w = f2tf32(w.w);
            *(float4*)&Ws[r][c4 * 4] = w;
        }
        __syncthreads();
        #pragma unroll
        for (int kk = 0; kk < 8; kk++) {
            wmma::fragment<wmma::matrix_a, 16, 16, 8, wmma::precision::tf32, wmma::row_major> a[2];
            wmma::fragment<wmma::matrix_b, 16, 16, 8, wmma::precision::tf32, wmma::row_major> bfr[2];
            #pragma unroll
            for (int i = 0; i < 2; i++)
                wmma::load_matrix_sync(a[i], &Xs[warp_m + 16 * i][kk * 8], 72);
            #pragma unroll
            for (int j = 0; j < 2; j++)
                wmma::load_matrix_sync(bfr[j], &Ws[kk * 8][warp_n + 16 * j], 72);
            #pragma unroll
            for (int i = 0; i < 2; i++)
                #pragma unroll
                for (int j = 0; j < 2; j++)
                    wmma::mma_sync(c[i][j], a[i], bfr[j], c[i][j]);
        }
        __syncthreads();
    }

    __shared__ float Stage[64][72];
    #pragma unroll
    for (int i = 0; i < 2; i++)
        #pragma unroll
        for (int j = 0; j < 2; j++)
            wmma::store_matrix_sync(&Stage[warp_m + 16 * i][warp_n + 16 * j], c[i][j], 72,
                                    wmma::mem_row_major);
    __syncthreads();
    #pragma unroll
    for (int i = 0; i < 8; i++) {
        int idx = t + i * 128;
        int r = idx >> 4, c4 = idx & 15;
        float4 v = *(float4*)&Stage[r][c4 * 4];
        float4 bb = *(const float4*)&bias[col0 + c4 * 4];
        v.x = f2tf32(v.x + bb.x); v.y = f2tf32(v.y + bb.y);
        v.z = f2tf32(v.z + bb.z); v.w = f2tf32(v.w + bb.w);
        *(float4*)&g_h[(size_t)(row0 + r) * HD + col0 + c4 * 4] = v;
    }
}

// ---------------------------------------------------------------------------
// K2: register-resident fused attention (raw mma.sync tf32)
// CTA: 256 threads / 8 warps; each warp owns 16 q-rows -> 128-row tile.
// 2 CTAs per SM so barrier/memory stalls are covered.
// ---------------------------------------------------------------------------
#define KSTR 68   // smem tile stride (floats)

__global__ __launch_bounds__(256, 2) void k_fused() {
    __shared__ float buf[2][64 * KSTR];

    const int t = threadIdx.x;
    const int lane = t & 31;
    const int wid = t >> 5;                 // 0..7
    const int g = lane >> 2;                // 0..7
    const int q = lane & 3;                 // 0..3
    const int row0 = blockIdx.x * 128;
    const int bh = blockIdx.y;
    const int b = bh >> 3, hh = bh & 7;

    const float* Hb = g_h + (size_t)b * NN * HD + hh * DD;
    const int r_lo = row0 + wid * 16 + g;
    const int r_hi = r_lo + 8;

    // prefetch K/V tile 0 via cp.async (64 rows x 64 cols)
    {
        #pragma unroll
        for (int k = 0; k < 4; k++) {
            int c = t + k * 256;             // 0..1023
            int r = c >> 4, seg = c & 15;
            unsigned dst = (unsigned)__cvta_generic_to_shared(&buf[0][r * KSTR + seg * 4]);
            const float* src = &Hb[(size_t)r * HD + seg * 4];
            asm volatile("cp.async.ca.shared.global [%0], [%1], 16;" :: "r"(dst), "l"(src));
        }
        asm volatile("cp.async.commit_group;");
    }

    // Q fragments (g_h pre-rounded to tf32)
    unsigned Qa[8][4];
    #pragma unroll
    for (int kc = 0; kc < 8; kc++) {
        Qa[kc][0] = __float_as_uint(Hb[(size_t)r_lo * HD + 8 * kc + q]);
        Qa[kc][1] = __float_as_uint(Hb[(size_t)r_hi * HD + 8 * kc + q]);
        Qa[kc][2] = __float_as_uint(Hb[(size_t)r_lo * HD + 8 * kc + q + 4]);
        Qa[kc][3] = __float_as_uint(Hb[(size_t)r_hi * HD + 8 * kc + q + 4]);
    }

    float Oa[8][4];
    #pragma unroll
    for (int f = 0; f < 8; f++)
        #pragma unroll
        for (int e = 0; e < 4; e++) Oa[f][e] = 0.f;
    float rs_lo = 0.f, rs_hi = 0.f;

    const unsigned* mrow_lo = &g_mask[((size_t)b * NN + r_lo) * NW];
    const unsigned* mrow_hi = &g_mask[((size_t)b * NN + r_hi) * NW];
    float* Srow_lo = &g_S[((size_t)bh * NN + r_lo) * NN];
    float* Srow_hi = &g_S[((size_t)bh * NN + r_hi) * NN];

    for (int it = 0; it < 32; it++) {
        const int m0 = it * 64;
        asm volatile("cp.async.wait_group 0;");
        __syncthreads();

        if (it < 31) {
            #pragma unroll
            for (int k = 0; k < 4; k++) {
                int c = t + k * 256;
                int r = c >> 4, seg = c & 15;
                unsigned dst = (unsigned)__cvta_generic_to_shared(
                    &buf[(it + 1) & 1][r * KSTR + seg * 4]);
                const float* src = &Hb[(size_t)(m0 + 64 + r) * HD + seg * 4];
                asm volatile("cp.async.ca.shared.global [%0], [%1], 16;" :: "r"(dst), "l"(src));
            }
            asm volatile("cp.async.commit_group;");
        }

        const float* Kb = buf[it & 1];

        const unsigned m00 = __ldg(&mrow_lo[it * 2]);
        const unsigned m01 = __ldg(&mrow_lo[it * 2 + 1]);
        const unsigned m10 = __ldg(&mrow_hi[it * 2]);
        const unsigned m11 = __ldg(&mrow_hi[it * 2 + 1]);

        // ---- S = Q K^T ----
        float Sa[8][4];
        #pragma unroll
        for (int f = 0; f < 8; f++)
            #pragma unroll
            for (int e = 0; e < 4; e++) Sa[f][e] = 0.f;

        #pragma unroll
        for (int f = 0; f < 8; f++) {
            #pragma unroll
            for (int kc = 0; kc < 8; kc++) {
                unsigned b0 = __float_as_uint(Kb[(8 * f + g) * KSTR + 8 * kc + q]);
                unsigned b1 = __float_as_uint(Kb[(8 * f + g) * KSTR + 8 * kc + q + 4]);
                mma_tf32(Sa[f], Qa[kc][0], Qa[kc][1], Qa[kc][2], Qa[kc][3], b0, b1);
            }
        }

        // ---- mask + exp + rowsum + stream E (unrounded; mma truncates in HW) ----
        #pragma unroll
        for (int f = 0; f < 8; f++) {
            const unsigned wlo = (f < 4) ? m00 : m01;
            const unsigned whi = (f < 4) ? m10 : m11;
            const int sh = (8 * f + 2 * q) & 31;
            float e0 = ((wlo >> sh) & 1u)       ? __expf(Sa[f][0] * SCALE) : 0.f;
            float e1 = ((wlo >> (sh + 1)) & 1u) ? __expf(Sa[f][1] * SCALE) : 0.f;
            float e2 = ((whi >> sh) & 1u)       ? __expf(Sa[f][2] * SCALE) : 0.f;
            float e3 = ((whi >> (sh + 1)) & 1u) ? __expf(Sa[f][3] * SCALE) : 0.f;
            rs_lo += e0 + e1;
            rs_hi += e2 + e3;
            Sa[f][0] = e0; Sa[f][1] = e1; Sa[f][2] = e2; Sa[f][3] = e3;
            __stcs((float2*)&Srow_lo[m0 + 8 * f + 2 * q], make_float2(e0, e1));
            __stcs((float2*)&Srow_hi[m0 + 8 * f + 2 * q], make_float2(e2, e3));
        }

        // ---- O += E V  (A fragments from Sa via intra-quad shuffles) ----
        const int src1 = (lane & ~3) | (q >> 1);
        const int src2 = src1 + 2;
        const bool odd = q & 1;
        #pragma unroll
        for (int kc = 0; kc < 8; kc++) {
            float c0 = Sa[kc][0], c1 = Sa[kc][1], c2 = Sa[kc][2], c3 = Sa[kc][3];
            float v00 = __shfl_sync(0xffffffffu, c0, src1);
            float v01 = __shfl_sync(0xffffffffu, c1, src1);
            float v02 = __shfl_sync(0xffffffffu, c2, src1);
            float v03 = __shfl_sync(0xffffffffu, c3, src1);
            float v10 = __shfl_sync(0xffffffffu, c0, src2);
            float v11 = __shfl_sync(0xffffffffu, c1, src2);
            float v12 = __shfl_sync(0xffffffffu, c2, src2);
            float v13 = __shfl_sync(0xffffffffu, c3, src2);
            unsigned a0 = __float_as_uint(odd ? v01 : v00);
            unsigned a1 = __float_as_uint(odd ? v03 : v02);
            unsigned a2 = __float_as_uint(odd ? v11 : v10);
            unsigned a3 = __float_as_uint(odd ? v13 : v12);
            #pragma unroll
            for (int df = 0; df < 8; df++) {
                unsigned b0 = __float_as_uint(Kb[(8 * kc + q) * KSTR + 8 * df + g]);
                unsigned b1 = __float_as_uint(Kb[(8 * kc + q + 4) * KSTR + 8 * df + g]);
                mma_tf32(Oa[df], a0, a1, a2, a3, b0, b1);
            }
        }
    }

    // ---- epilogue ----
    rs_lo += __shfl_xor_sync(0xffffffffu, rs_lo, 1);
    rs_lo += __shfl_xor_sync(0xffffffffu, rs_lo, 2);
    rs_hi += __shfl_xor_sync(0xffffffffu, rs_hi, 1);
    rs_hi += __shfl_xor_sync(0xffffffffu, rs_hi, 2);
    if (q == 0) {
        g_rowsum[(size_t)bh * NN + r_lo] = rs_lo;
        g_rowsum[(size_t)bh * NN + r_hi] = rs_hi;
    }
    const float inv_lo = 1.f / rs_lo;
    const float inv_hi = 1.f / rs_hi;
    float* O_lo = &g_O[((size_t)b * NN + r_lo) * HD + hh * DD];
    float* O_hi = &g_O[((size_t)b * NN + r_hi) * HD + hh * DD];
    #pragma unroll
    for (int df = 0; df < 8; df++) {
        *(float2*)&O_lo[8 * df + 2 * q] = make_float2(Oa[df][0] * inv_lo, Oa[df][1] * inv_lo);
        *(float2*)&O_hi[8 * df + 2 * q] = make_float2(Oa[df][2] * inv_hi, Oa[df][3] * inv_hi);
    }
}

// ---------------------------------------------------------------------------
// K3: mean over heads of p = e / rowsum  -> out_mean
// ---------------------------------------------------------------------------
__global__ void k_mean(float* __restrict__ out_mean) {
    __shared__ float inv[HH];
    const int row = blockIdx.x;
    const int b = row >> 11;
    const int n = row & (NN - 1);
    const int t = threadIdx.x;

    if (t < HH) inv[t] = 0.125f / g_rowsum[(size_t)(b * HH + t) * NN + n];
    __syncthreads();

    float* mrow = out_mean + (size_t)row * NN;
    #pragma unroll
    for (int c4 = t; c4 < NN / 4; c4 += 256) {
        float4 acc = make_float4(0.f, 0.f, 0.f, 0.f);
        #pragma unroll
        for (int h = 0; h < HH; h++) {
            const float4 e4 = __ldcs((const float4*)&g_S[((size_t)(b * HH + h) * NN + n) * NN + c4 * 4]);
            float iv = inv[h];
            acc.x += e4.x * iv; acc.y += e4.y * iv;
            acc.z += e4.z * iv; acc.w += e4.w * iv;
        }
        *(float4*)&mrow[c4 * 4] = acc;
    }
}

// ---------------------------------------------------------------------------
// K5: LayerNorm -> out
// ---------------------------------------------------------------------------
__global__ void k_ln(const float* __restrict__ gamma, const float* __restrict__ beta,
                     float* __restrict__ out) {
    __shared__ float red[128];
    __shared__ float red2[128];

    const int row = blockIdx.x;
    const int t = threadIdx.x;
    const float* v = g_O + (size_t)row * HD;

    float s = 0.f, s2 = 0.f;
    float vals[4];
    #pragma unroll
    for (int i = 0; i < 4; i++) {
        vals[i] = v[t + i * 128];
        s += vals[i];
        s2 += vals[i] * vals[i];
    }
    red[t] = s; red2[t] = s2;
    __syncthreads();
    for (int st = 64; st > 0; st >>= 1) {
        if (t < st) { red[t] += red[t + st]; red2[t] += red2[t + st]; }
        __syncthreads();
    }
    const float mu = red[0] * (1.f / HD);
    const float var = red2[0] * (1.f / HD) - mu * mu;
    const float rstd = rsqrtf(var + EPS);

    float* orow = out + (size_t)row * HD;
    #pragma unroll
    for (int i = 0; i < 4; i++) {
        int c = t + i * 128;
        orow[c] = (vals[i] - mu) * rstd * gamma[c] + beta[c];
    }
}

// ---------------------------------------------------------------------------
extern "C" void kernel_launch(void* const* d_in, const int* in_sizes, int n_in,
                              void* d_out, int out_size) {
    const float* x     = (const float*)d_in[0];
    const int*   adj   = (const int*)d_in[1];
    const float* W_w   = (const float*)d_in[2];
    const float* W_b   = (const float*)d_in[3];
    const float* gamma = (const float*)d_in[4];
    const float* beta  = (const float*)d_in[5];
    float* out = (float*)d_out;
    float* out_mean = out + (size_t)BB * NN * HD;

    k_pack<<<BB * NN, 256>>>(adj);
    k_proj<<<dim3(HD / 64, (BB * NN) / 64), 128>>>(x, W_w, W_b);
    k_fused<<<dim3(NN / 128, BB * HH), 256>>>();
    k_mean<<<BB * NN, 256>>>(out_mean);
    k_ln<<<BB * NN, 128>>>(gamma, beta, out);
}